// round 4
// baseline (speedup 1.0000x reference)
#include <cuda_runtime.h>
#include <cuda_bf16.h>

// GConv: agg = segment_sum(concat(feat[src], edge_feat), dst); out = feat + agg@W + b
// R3: atomic scatter replaced by on-device CSR build + warp-per-node gather
// aggregation (no f32 atomics), plus float4-LDS GEMM inner loop.
//
// src/dst are int32 (JAX x64 disabled downcasts jnp.int64 -> int32).

#define MAX_NODES 50000
#define MAX_EDGES 800000
#define AGG_DIM   160
#define F_DIM     128
#define E_DIM     32

__device__ __align__(128) float g_agg[(size_t)MAX_NODES * AGG_DIM];
__device__ int  g_counts[MAX_NODES];
__device__ int  g_offsets[MAX_NODES + 1];
__device__ int  g_cursor[MAX_NODES];
__device__ int2 g_csr[MAX_EDGES];        // (src_node, edge_id) sorted by dst bucket

// ---------------------------------------------------------------------------
// 1) zero the per-node edge counters
// ---------------------------------------------------------------------------
__global__ void zero_counts_kernel(int N) {
    int stride = gridDim.x * blockDim.x;
    for (int i = blockIdx.x * blockDim.x + threadIdx.x; i < N; i += stride)
        g_counts[i] = 0;
}

// ---------------------------------------------------------------------------
// 2) histogram of dst
// ---------------------------------------------------------------------------
__global__ void hist_kernel(const int* __restrict__ dst, int E, int N) {
    int stride = gridDim.x * blockDim.x;
    for (int e = blockIdx.x * blockDim.x + threadIdx.x; e < E; e += stride) {
        int d = dst[e];
        if ((unsigned)d < (unsigned)N) atomicAdd(&g_counts[d], 1);
    }
}

// ---------------------------------------------------------------------------
// 3) single-block exclusive scan over counts -> offsets (+ cursor copy)
// ---------------------------------------------------------------------------
__global__ void scan_kernel(int N) {
    const int T = 1024;
    __shared__ int part[T];
    const int tid = threadIdx.x;
    const int per = (N + T - 1) / T;
    const int beg = tid * per;
    const int end = min(beg + per, N);

    int sum = 0;
    for (int i = beg; i < end; i++) sum += g_counts[i];
    part[tid] = sum;
    __syncthreads();

    // Hillis-Steele inclusive scan over the 1024 partials
    for (int off = 1; off < T; off <<= 1) {
        int t = 0;
        if (tid >= off) t = part[tid - off];
        __syncthreads();
        if (tid >= off) part[tid] += t;
        __syncthreads();
    }

    int prefix = (tid == 0) ? 0 : part[tid - 1];
    for (int i = beg; i < end; i++) {
        int c = g_counts[i];
        g_offsets[i] = prefix;
        g_cursor[i]  = prefix;
        prefix += c;
    }
    if (tid == 0) g_offsets[N] = part[T - 1];
}

// ---------------------------------------------------------------------------
// 4) fill CSR slots: csr[pos] = (src, edge_id)
// ---------------------------------------------------------------------------
__global__ void fill_csr_kernel(const int* __restrict__ src,
                                const int* __restrict__ dst,
                                int E, int N) {
    int stride = gridDim.x * blockDim.x;
    for (int e = blockIdx.x * blockDim.x + threadIdx.x; e < E; e += stride) {
        int s = src[e];
        int d = dst[e];
        if ((unsigned)s >= (unsigned)N || (unsigned)d >= (unsigned)N) continue;
        int pos = atomicAdd(&g_cursor[d], 1);
        g_csr[pos] = make_int2(s, e);
    }
}

// ---------------------------------------------------------------------------
// 5) warp-per-node gather aggregation (register accumulators, one store)
//    lane carries float4 of the 128-dim h part; lanes 0..7 also carry the
//    32-dim edge part. No atomics.
// ---------------------------------------------------------------------------
__global__ void aggregate_kernel(const float* __restrict__ feat,
                                 const float* __restrict__ edge_feat,
                                 int N) {
    const int warps_per_block = blockDim.x >> 5;
    const int node = blockIdx.x * warps_per_block + (threadIdx.x >> 5);
    const int lane = threadIdx.x & 31;
    if (node >= N) return;

    const int beg = g_offsets[node];
    const int end = g_offsets[node + 1];

    float4 acc_h = make_float4(0.f, 0.f, 0.f, 0.f);
    float4 acc_e = make_float4(0.f, 0.f, 0.f, 0.f);

    const float4* featv = reinterpret_cast<const float4*>(feat);
    const float4* edgev = reinterpret_cast<const float4*>(edge_feat);

    int j = beg;
    // unroll by 2 for memory-level parallelism
    for (; j + 1 < end; j += 2) {
        int2 a = g_csr[j];
        int2 c = g_csr[j + 1];
        float4 h0 = featv[(long long)a.x * (F_DIM / 4) + lane];
        float4 h1 = featv[(long long)c.x * (F_DIM / 4) + lane];
        float4 e0, e1;
        if (lane < E_DIM / 4) {
            e0 = edgev[(long long)a.y * (E_DIM / 4) + lane];
            e1 = edgev[(long long)c.y * (E_DIM / 4) + lane];
        }
        acc_h.x += h0.x + h1.x; acc_h.y += h0.y + h1.y;
        acc_h.z += h0.z + h1.z; acc_h.w += h0.w + h1.w;
        if (lane < E_DIM / 4) {
            acc_e.x += e0.x + e1.x; acc_e.y += e0.y + e1.y;
            acc_e.z += e0.z + e1.z; acc_e.w += e0.w + e1.w;
        }
    }
    if (j < end) {
        int2 a = g_csr[j];
        float4 h0 = featv[(long long)a.x * (F_DIM / 4) + lane];
        acc_h.x += h0.x; acc_h.y += h0.y; acc_h.z += h0.z; acc_h.w += h0.w;
        if (lane < E_DIM / 4) {
            float4 e0 = edgev[(long long)a.y * (E_DIM / 4) + lane];
            acc_e.x += e0.x; acc_e.y += e0.y; acc_e.z += e0.z; acc_e.w += e0.w;
        }
    }

    float4* row = reinterpret_cast<float4*>(g_agg + (long long)node * AGG_DIM);
    row[lane] = acc_h;
    if (lane < E_DIM / 4) row[F_DIM / 4 + lane] = acc_e;
}

// ---------------------------------------------------------------------------
// 6) GEMM + bias + residual. W [160,128] in smem; 8 rows/pass; float4 LDS A.
// ---------------------------------------------------------------------------
#define RPB 8
#define GEMM_SMEM ((AGG_DIM * F_DIM + RPB * AGG_DIM) * (int)sizeof(float))  // 87040

__global__ void gemm_kernel(const float* __restrict__ feat,
                            const float* __restrict__ W,
                            const float* __restrict__ b,
                            float* __restrict__ out,
                            int N) {
    extern __shared__ float sh[];
    float* Wsh = sh;                      // 160*128 floats (80KB)
    float* Ash = sh + AGG_DIM * F_DIM;    // RPB*160 floats (5KB)

    const int tid = threadIdx.x;          // output column

    {
        float4* Wv = reinterpret_cast<float4*>(Wsh);
        const float4* Wg = reinterpret_cast<const float4*>(W);
        const int n4 = AGG_DIM * F_DIM / 4;
        for (int i = tid; i < n4; i += 128) Wv[i] = Wg[i];
    }
    const float bias = b[tid];
    __syncthreads();

    const int nchunks = (N + RPB - 1) / RPB;
    for (int chunk = blockIdx.x; chunk < nchunks; chunk += gridDim.x) {
        const int row0 = chunk * RPB;
        const int nrows = min(RPB, N - row0);

        {
            const float4* Ag = reinterpret_cast<const float4*>(g_agg + (long long)row0 * AGG_DIM);
            float4* Av = reinterpret_cast<float4*>(Ash);
            const int n4 = nrows * AGG_DIM / 4;
            for (int i = tid; i < n4; i += 128) Av[i] = Ag[i];
        }
        __syncthreads();

        float acc[RPB];
#pragma unroll
        for (int r = 0; r < RPB; r++) acc[r] = bias;

        for (int k = 0; k < AGG_DIM; k += 4) {
            float4 av[RPB];
#pragma unroll
            for (int r = 0; r < RPB; r++)
                av[r] = *reinterpret_cast<const float4*>(&Ash[r * AGG_DIM + k]);
#pragma unroll
            for (int kk = 0; kk < 4; kk++) {
                const float w = Wsh[(k + kk) * F_DIM + tid];
#pragma unroll
                for (int r = 0; r < RPB; r++) {
                    const float a = (kk == 0) ? av[r].x : (kk == 1) ? av[r].y
                                  : (kk == 2) ? av[r].z : av[r].w;
                    acc[r] += a * w;
                }
            }
        }

#pragma unroll
        for (int r = 0; r < RPB; r++) {
            if (r < nrows) {
                const long long off = (long long)(row0 + r) * F_DIM + tid;
                out[off] = feat[off] + acc[r];
            }
        }
        __syncthreads();
    }
}

// ---------------------------------------------------------------------------
// Launch
// ---------------------------------------------------------------------------
extern "C" void kernel_launch(void* const* d_in, const int* in_sizes, int n_in,
                              void* d_out, int out_size) {
    const float* feat      = (const float*)d_in[0];
    const float* edge_feat = (const float*)d_in[1];
    const int*   src       = (const int*)d_in[2];
    const int*   dst       = (const int*)d_in[3];
    const float* W         = (const float*)d_in[4];
    const float* b         = (const float*)d_in[5];
    float*       out       = (float*)d_out;

    int N = out_size / F_DIM;             // 50000
    int E = in_sizes[2];                  // 800000
    if (N > MAX_NODES) N = MAX_NODES;
    if (E > MAX_EDGES) E = MAX_EDGES;

    zero_counts_kernel<<<64, 256>>>(N);
    if (E > 0) {
        const int eb = (E + 255) / 256;
        hist_kernel<<<eb, 256>>>(dst, E, N);
        scan_kernel<<<1, 1024>>>(N);
        fill_csr_kernel<<<eb, 256>>>(src, dst, E, N);
    } else {
        scan_kernel<<<1, 1024>>>(N);
    }

    {
        const int wpb = 8;                // 256 threads = 8 warps = 8 nodes/CTA
        const int blocks = (N + wpb - 1) / wpb;
        aggregate_kernel<<<blocks, 256>>>(feat, edge_feat, N);
    }

    {
        cudaFuncSetAttribute(gemm_kernel, cudaFuncAttributeMaxDynamicSharedMemorySize, GEMM_SMEM);
        gemm_kernel<<<296, 128, GEMM_SMEM>>>(feat, W, b, out, N);
    }
}

// round 6
// speedup vs baseline: 1.2419x; 1.2419x over previous
#include <cuda_runtime.h>
#include <cuda_bf16.h>

// GConv: agg = segment_sum(concat(feat[src], edge_feat), dst); out = feat + agg@W + b
// R5 (resubmit of R4 + overflow spill hardening):
//   single-pass bucket build (no hist/scan), shuffle-staged gather aggregate
//   (no f32 atomics, high MLP), register-blocked GEMM with fused bias+residual.
//
// src/dst are int32 (JAX x64 disabled downcasts jnp.int64 -> int32).

#define MAX_NODES 50000
#define MAX_EDGES 800000
#define AGG_DIM   160
#define F_DIM     128
#define E_DIM     32
#define CAP       64      // per-node bucket capacity (degrees ~Poisson(16), max ~45)
#define SPILL_CAP 4096    // safety net for bucket overflow (expected empty)

__device__ __align__(128) float g_agg[(size_t)MAX_NODES * AGG_DIM];
__device__ int  g_counts[MAX_NODES];
__device__ __align__(16) int2 g_bucket[(size_t)MAX_NODES * CAP];   // (src, edge_id)
__device__ int  g_spill_n;
__device__ int4 g_spill[SPILL_CAP];      // (dst, src, edge_id, pad)

// ---------------------------------------------------------------------------
// 1a/1b) zero per-node counters (+ spill count), split into two launches so
//        ncu's captured launch index (#4, -s 5 -c 1 from a skipped prefix)
//        lands on the aggregate kernel.
// ---------------------------------------------------------------------------
__global__ void zero_counts_kernel(int beg, int end) {
    int stride = gridDim.x * blockDim.x;
    for (int i = beg + blockIdx.x * blockDim.x + threadIdx.x; i < end; i += stride)
        g_counts[i] = 0;
    if (beg == 0 && blockIdx.x == 0 && threadIdx.x == 0) g_spill_n = 0;
}

// ---------------------------------------------------------------------------
// 2) single-pass bucket fill: 4 edges/thread, int4 index loads (MLP=4)
// ---------------------------------------------------------------------------
__global__ void fill_buckets_kernel(const int* __restrict__ src,
                                    const int* __restrict__ dst,
                                    int E, int N) {
    const int t = blockIdx.x * blockDim.x + threadIdx.x;
    const int base = t * 4;
    if (base >= E) return;

    int s[4], d[4];
    if (base + 3 < E) {
        int4 sv = *reinterpret_cast<const int4*>(src + base);
        int4 dv = *reinterpret_cast<const int4*>(dst + base);
        s[0] = sv.x; s[1] = sv.y; s[2] = sv.z; s[3] = sv.w;
        d[0] = dv.x; d[1] = dv.y; d[2] = dv.z; d[3] = dv.w;
    } else {
#pragma unroll
        for (int k = 0; k < 4; k++) {
            if (base + k < E) { s[k] = src[base + k]; d[k] = dst[base + k]; }
            else              { s[k] = -1; d[k] = -1; }
        }
    }

#pragma unroll
    for (int k = 0; k < 4; k++) {
        if ((unsigned)d[k] < (unsigned)N && (unsigned)s[k] < (unsigned)N) {
            int pos = atomicAdd(&g_counts[d[k]], 1);
            if (pos < CAP) {
                g_bucket[(size_t)d[k] * CAP + pos] = make_int2(s[k], base + k);
            } else {
                int sp = atomicAdd(&g_spill_n, 1);
                if (sp < SPILL_CAP)
                    g_spill[sp] = make_int4(d[k], s[k], base + k, 0);
            }
        }
    }
}

// ---------------------------------------------------------------------------
// 3) warp-per-node gather aggregation.
//    Lane l preloads bucket entries l and 32+l; per 4-edge group the indices
//    are distributed via SHFL (independent, lat ~26) so the 4 feature loads
//    of each group are fully independent -> high MLP, short per-node chain.
//    A (normally empty) spill list covers bucket overflow.
// ---------------------------------------------------------------------------
__global__ void aggregate_kernel(const float* __restrict__ feat,
                                 const float* __restrict__ edge_feat,
                                 int N) {
    const int warps_per_block = blockDim.x >> 5;
    const int node = blockIdx.x * warps_per_block + (threadIdx.x >> 5);
    const int lane = threadIdx.x & 31;
    if (node >= N) return;

    int deg = g_counts[node];
    if (deg > CAP) deg = CAP;

    const int2* bk = g_bucket + (size_t)node * CAP;
    // preload: lane l holds entries l and 32+l (coalesced 256B + 256B)
    int2 m0 = bk[lane];
    int2 m1 = bk[32 + lane];

    float4 acc_h = make_float4(0.f, 0.f, 0.f, 0.f);
    float4 acc_e = make_float4(0.f, 0.f, 0.f, 0.f);

    const float4* featv = reinterpret_cast<const float4*>(feat);
    const float4* edgev = reinterpret_cast<const float4*>(edge_feat);

    for (int e0 = 0; e0 < deg; e0 += 4) {
#pragma unroll
        for (int k = 0; k < 4; k++) {
            const int e = e0 + k;                       // uniform across warp
            const int sv = (e < 32) ? m0.x : m1.x;
            const int iv = (e < 32) ? m0.y : m1.y;
            const int s  = __shfl_sync(0xffffffffu, sv, e & 31);
            const int id = __shfl_sync(0xffffffffu, iv, e & 31);
            if (e < deg) {
                float4 h = featv[(size_t)s * (F_DIM / 4) + lane];
                acc_h.x += h.x; acc_h.y += h.y; acc_h.z += h.z; acc_h.w += h.w;
                if (lane < E_DIM / 4) {
                    float4 ev = edgev[(size_t)id * (E_DIM / 4) + lane];
                    acc_e.x += ev.x; acc_e.y += ev.y; acc_e.z += ev.z; acc_e.w += ev.w;
                }
            }
        }
    }

    // overflow spill (expected empty; one cheap uniform load when n==0)
    int spn = g_spill_n;
    if (spn > 0) {
        if (spn > SPILL_CAP) spn = SPILL_CAP;
        for (int i = 0; i < spn; i++) {
            int4 sp = g_spill[i];
            if (sp.x == node) {
                float4 h = featv[(size_t)sp.y * (F_DIM / 4) + lane];
                acc_h.x += h.x; acc_h.y += h.y; acc_h.z += h.z; acc_h.w += h.w;
                if (lane < E_DIM / 4) {
                    float4 ev = edgev[(size_t)sp.z * (E_DIM / 4) + lane];
                    acc_e.x += ev.x; acc_e.y += ev.y; acc_e.z += ev.z; acc_e.w += ev.w;
                }
            }
        }
    }

    float4* row = reinterpret_cast<float4*>(g_agg + (size_t)node * AGG_DIM);
    row[lane] = acc_h;
    if (lane < E_DIM / 4) row[F_DIM / 4 + lane] = acc_e;
}

// ---------------------------------------------------------------------------
// 4) GEMM + bias + residual. W [160,128] in smem; 8 rows/pass; float4 LDS A.
// ---------------------------------------------------------------------------
#define RPB 8
#define GEMM_SMEM ((AGG_DIM * F_DIM + RPB * AGG_DIM) * (int)sizeof(float))  // 87040

__global__ void gemm_kernel(const float* __restrict__ feat,
                            const float* __restrict__ W,
                            const float* __restrict__ b,
                            float* __restrict__ out,
                            int N) {
    extern __shared__ float sh[];
    float* Wsh = sh;                      // 160*128 floats (80KB)
    float* Ash = sh + AGG_DIM * F_DIM;    // RPB*160 floats (5KB)

    const int tid = threadIdx.x;          // output column

    {
        float4* Wv = reinterpret_cast<float4*>(Wsh);
        const float4* Wg = reinterpret_cast<const float4*>(W);
        const int n4 = AGG_DIM * F_DIM / 4;
        for (int i = tid; i < n4; i += 128) Wv[i] = Wg[i];
    }
    const float bias = b[tid];
    __syncthreads();

    const int nchunks = (N + RPB - 1) / RPB;
    for (int chunk = blockIdx.x; chunk < nchunks; chunk += gridDim.x) {
        const int row0 = chunk * RPB;
        const int nrows = min(RPB, N - row0);

        {
            const float4* Ag = reinterpret_cast<const float4*>(g_agg + (size_t)row0 * AGG_DIM);
            float4* Av = reinterpret_cast<float4*>(Ash);
            const int n4 = nrows * AGG_DIM / 4;
            for (int i = tid; i < n4; i += 128) Av[i] = Ag[i];
        }
        __syncthreads();

        float acc[RPB];
#pragma unroll
        for (int r = 0; r < RPB; r++) acc[r] = bias;

        for (int k = 0; k < AGG_DIM; k += 4) {
            float4 av[RPB];
#pragma unroll
            for (int r = 0; r < RPB; r++)
                av[r] = *reinterpret_cast<const float4*>(&Ash[r * AGG_DIM + k]);
#pragma unroll
            for (int kk = 0; kk < 4; kk++) {
                const float w = Wsh[(k + kk) * F_DIM + tid];
#pragma unroll
                for (int r = 0; r < RPB; r++) {
                    const float a = (kk == 0) ? av[r].x : (kk == 1) ? av[r].y
                                  : (kk == 2) ? av[r].z : av[r].w;
                    acc[r] += a * w;
                }
            }
        }

#pragma unroll
        for (int r = 0; r < RPB; r++) {
            if (r < nrows) {
                const size_t off = (size_t)(row0 + r) * F_DIM + tid;
                out[off] = feat[off] + acc[r];
            }
        }
        __syncthreads();
    }
}

// ---------------------------------------------------------------------------
// Launch: zeroA(1) zeroB(2) fill(3) aggregate(4) gemm(5)
// ---------------------------------------------------------------------------
extern "C" void kernel_launch(void* const* d_in, const int* in_sizes, int n_in,
                              void* d_out, int out_size) {
    const float* feat      = (const float*)d_in[0];
    const float* edge_feat = (const float*)d_in[1];
    const int*   src       = (const int*)d_in[2];
    const int*   dst       = (const int*)d_in[3];
    const float* W         = (const float*)d_in[4];
    const float* b         = (const float*)d_in[5];
    float*       out       = (float*)d_out;

    int N = out_size / F_DIM;             // 50000
    int E = in_sizes[2];                  // 800000
    if (N > MAX_NODES) N = MAX_NODES;
    if (E > MAX_EDGES) E = MAX_EDGES;

    const int half = N / 2;
    zero_counts_kernel<<<64, 256>>>(0, half);
    zero_counts_kernel<<<64, 256>>>(half, N);

    if (E > 0) {
        const int threads = (E + 3) / 4;
        fill_buckets_kernel<<<(threads + 255) / 256, 256>>>(src, dst, E, N);
    }

    {
        const int wpb = 8;                // 256 threads = 8 warps = 8 nodes/CTA
        const int blocks = (N + wpb - 1) / wpb;
        aggregate_kernel<<<blocks, 256>>>(feat, edge_feat, N);
    }

    {
        cudaFuncSetAttribute(gemm_kernel, cudaFuncAttributeMaxDynamicSharedMemorySize, GEMM_SMEM);
        gemm_kernel<<<296, 128, GEMM_SMEM>>>(feat, W, b, out, N);
    }
}